// round 4
// baseline (speedup 1.0000x reference)
#include <cuda_runtime.h>

// Problem constants
#define B_  32
#define IC_ 1152
#define OC_ 10
#define ID_ 8
#define OD_ 16
#define N_ITER_ 5
#define EPS_ 1e-20f

#define GI_   4            // ic's per CTA
#define NBLK_ (IC_ / GI_)  // 288 CTAs
#define NTHR_ (OC_ * 32)   // 320 threads: warp = oc, lane = b

__device__ __forceinline__ float frcp(float a) {
    float r;
    asm("rcp.approx.f32 %0, %1;" : "=f"(r) : "f"(a));
    return r;
}

__global__ void caps_zero_kernel(float* out, int n) {
    int i = blockIdx.x * blockDim.x + threadIdx.x;
    if (i < n) out[i] = 0.0f;
}

__global__ __launch_bounds__(NTHR_, 2)
void caps_main_kernel(const float* __restrict__ x,
                      const float* __restrict__ w,
                      float* __restrict__ out)
{
    __shared__ float sw[OC_ * ID_ * OD_];   // 1280 floats: weights for current ic
    __shared__ float salpha[OC_][32];       // alpha exchange across warps

    const int tid = threadIdx.x;
    const int c   = tid >> 5;    // warp id -> output capsule
    const int b   = tid & 31;    // lane    -> batch
    const int i0  = blockIdx.x * GI_;

    float oacc[OD_];
    #pragma unroll
    for (int e = 0; e < OD_; e++) oacc[e] = 0.0f;

    for (int ii = 0; ii < GI_; ii++) {
        const int i = i0 + ii;

        __syncthreads();  // previous iteration's smem reads complete

        // Cooperative load of w[i, :, :, :] (1280 floats) into smem, coalesced.
        {
            const float4* wg = reinterpret_cast<const float4*>(
                w + (size_t)i * (OC_ * ID_ * OD_));
            reinterpret_cast<float4*>(sw)[tid] = wg[tid];  // 320 * float4 = 1280
        }

        // Load + normalize this lane's x row: x[b, i, 0..7]
        float xn[ID_];
        {
            const float4* xp = reinterpret_cast<const float4*>(
                x + ((size_t)b * IC_ + i) * ID_);
            float4 a0 = xp[0], a1 = xp[1];
            xn[0] = a0.x; xn[1] = a0.y; xn[2] = a0.z; xn[3] = a0.w;
            xn[4] = a1.x; xn[5] = a1.y; xn[6] = a1.z; xn[7] = a1.w;
            float s = 0.0f;
            #pragma unroll
            for (int d = 0; d < ID_; d++) s += xn[d];
            float r = frcp(s + EPS_);
            #pragma unroll
            for (int d = 0; d < ID_; d++) xn[d] *= r;
        }

        __syncthreads();  // smem weights ready

        // This warp's capsule weights (uniform address across the warp:
        // smem broadcast, conflict-free).
        const float4* wrow4 = reinterpret_cast<const float4*>(sw) + c * (ID_ * OD_ / 4);

        // NNMF iterations (multiplicative update):
        //   s_d      = sum_e cur[e] * w[d,e]
        //   cur[e]  *= sum_d xn[d] * w[d,e] / (s_d + EPS)
        // Per-iteration renormalization of `cur` is omitted: the update is
        // scale-invariant in `cur` (k cancels between numerator and s_d),
        // and sum_e cur stays ~1 since xn is normalized. Normalize once at end.
        float cur[OD_];
        #pragma unroll
        for (int e = 0; e < OD_; e++) cur[e] = 1.0f / OD_;

        #pragma unroll
        for (int it = 0; it < N_ITER_; it++) {
            float acc[OD_];
            #pragma unroll
            for (int e = 0; e < OD_; e++) acc[e] = 0.0f;

            #pragma unroll
            for (int d = 0; d < ID_; d++) {
                float wr[OD_];
                #pragma unroll
                for (int k = 0; k < 4; k++) {
                    float4 v = wrow4[d * 4 + k];
                    wr[4*k + 0] = v.x; wr[4*k + 1] = v.y;
                    wr[4*k + 2] = v.z; wr[4*k + 3] = v.w;
                }
                float s = 0.0f;
                #pragma unroll
                for (int e = 0; e < OD_; e++) s += cur[e] * wr[e];
                float t = xn[d] * frcp(s + EPS_);
                #pragma unroll
                for (int e = 0; e < OD_; e++) acc[e] += wr[e] * t;
            }
            #pragma unroll
            for (int e = 0; e < OD_; e++) cur[e] *= acc[e];   // multiplicative update
        }

        // Final normalization -> h
        float hs = 0.0f;
        #pragma unroll
        for (int e = 0; e < OD_; e++) hs += cur[e];
        float hr = frcp(hs + EPS_);
        #pragma unroll
        for (int e = 0; e < OD_; e++) cur[e] *= hr;

        // alpha[b,i,c] = sum_d xn[d] * dot(h, w[d,:])
        float alpha = 0.0f;
        #pragma unroll
        for (int d = 0; d < ID_; d++) {
            float wr[OD_];
            #pragma unroll
            for (int k = 0; k < 4; k++) {
                float4 v = wrow4[d * 4 + k];
                wr[4*k + 0] = v.x; wr[4*k + 1] = v.y;
                wr[4*k + 2] = v.z; wr[4*k + 3] = v.w;
            }
            float s = 0.0f;
            #pragma unroll
            for (int e = 0; e < OD_; e++) s += cur[e] * wr[e];
            alpha += xn[d] * s;
        }

        salpha[c][b] = alpha;
        __syncthreads();

        // Normalize alpha over oc (10 warps); each lane sums its column.
        float asum = 0.0f;
        #pragma unroll
        for (int cc = 0; cc < OC_; cc++) asum += salpha[cc][b];
        float an = alpha * frcp(asum + EPS_);

        #pragma unroll
        for (int e = 0; e < OD_; e++) oacc[e] += cur[e] * an;
    }

    // Accumulate this CTA's contribution (sum over its 4 ic) into out[b,c,:].
    float* op = out + ((size_t)b * OC_ + c) * OD_;
    #pragma unroll
    for (int e = 0; e < OD_; e++) atomicAdd(op + e, oacc[e]);
}

extern "C" void kernel_launch(void* const* d_in, const int* in_sizes, int n_in,
                              void* d_out, int out_size)
{
    const float* x = (const float*)d_in[0];
    const float* w = (const float*)d_in[1];
    // Defensive: identify tensors by size (x = 294912, w = 1474560).
    if (n_in >= 2 && in_sizes[0] == IC_ * OC_ * ID_ * OD_) {
        const float* t = x; x = w; w = t;
    }
    float* out = (float*)d_out;

    caps_zero_kernel<<<(out_size + 255) / 256, 256>>>(out, out_size);
    caps_main_kernel<<<NBLK_, NTHR_>>>(x, w, out);
}

// round 5
// speedup vs baseline: 2.2304x; 2.2304x over previous
#include <cuda_runtime.h>

typedef unsigned long long ull;

// Problem constants
#define B_  32
#define IC_ 1152
#define OC_ 10
#define ID_ 8
#define OD_ 16
#define N_ITER_ 5
#define EPS_ 1e-20f

#define GI_   8            // ic's per CTA
#define NBLK_ (IC_ / GI_)  // 144 CTAs = one wave on 148 SMs
#define NTHR_ (OC_ * 32)   // 320 threads: warp = oc, lane = b

__device__ __forceinline__ float frcp(float a) {
    float r;
    asm("rcp.approx.f32 %0, %1;" : "=f"(r) : "f"(a));
    return r;
}

// Packed fp32x2 ops (sm_103a; ptxas never auto-fuses these from C++)
__device__ __forceinline__ ull FMA2(ull a, ull b, ull c) {
    ull d;
    asm("fma.rn.f32x2 %0, %1, %2, %3;" : "=l"(d) : "l"(a), "l"(b), "l"(c));
    return d;
}
__device__ __forceinline__ ull MUL2(ull a, ull b) {
    ull d;
    asm("mul.rn.f32x2 %0, %1, %2;" : "=l"(d) : "l"(a), "l"(b));
    return d;
}
__device__ __forceinline__ ull ADD2(ull a, ull b) {
    ull d;
    asm("add.rn.f32x2 %0, %1, %2;" : "=l"(d) : "l"(a), "l"(b));
    return d;
}
__device__ __forceinline__ ull PACK2(float lo, float hi) {
    ull d;
    asm("mov.b64 %0, {%1, %2};" : "=l"(d) : "f"(lo), "f"(hi));
    return d;
}
__device__ __forceinline__ float LO2(ull v) {
    float lo, hi;
    asm("mov.b64 {%0, %1}, %2;" : "=f"(lo), "=f"(hi) : "l"(v));
    return lo;
}
__device__ __forceinline__ float HI2(ull v) {
    float lo, hi;
    asm("mov.b64 {%0, %1}, %2;" : "=f"(lo), "=f"(hi) : "l"(v));
    return hi;
}
__device__ __forceinline__ float SUM2(ull v) {
    float lo, hi;
    asm("mov.b64 {%0, %1}, %2;" : "=f"(lo), "=f"(hi) : "l"(v));
    return lo + hi;
}

__global__ void caps_zero_kernel(float* out, int n) {
    int i = blockIdx.x * blockDim.x + threadIdx.x;
    if (i < n) out[i] = 0.0f;
}

__global__ __launch_bounds__(NTHR_, 1)
void caps_main_kernel(const float* __restrict__ x,
                      const float* __restrict__ w,
                      float* __restrict__ out)
{
    // Double-buffered per-ic weights + alpha exchange
    __shared__ __align__(16) float sw[2][OC_ * ID_ * OD_];  // 2 x 1280 floats
    __shared__ float salpha[OC_][32];

    const int tid = threadIdx.x;
    const int c   = tid >> 5;    // warp id -> output capsule
    const int b   = tid & 31;    // lane    -> batch
    const int i0  = blockIdx.x * GI_;

    ull oacc2[OD_ / 2];
    #pragma unroll
    for (int k = 0; k < OD_ / 2; k++) oacc2[k] = 0ULL;

    // ---- Prologue: load ic 0 weights + x row ----
    {
        const float4* wg = reinterpret_cast<const float4*>(
            w + (size_t)i0 * (OC_ * ID_ * OD_));
        reinterpret_cast<float4*>(sw[0])[tid] = wg[tid];  // 320 * float4 = 1280 fl
    }
    const float4* xbase = reinterpret_cast<const float4*>(
        x + ((size_t)b * IC_ + i0) * ID_);
    float4 xa = xbase[0], xb = xbase[1];
    __syncthreads();

    int pb = 0;
    for (int ii = 0; ii < GI_; ii++) {
        // ---- Prefetch next ic (global -> registers), hidden behind compute ----
        float4 wnext;
        float4 xna, xnb;
        if (ii + 1 < GI_) {
            const float4* wg = reinterpret_cast<const float4*>(
                w + (size_t)(i0 + ii + 1) * (OC_ * ID_ * OD_));
            wnext = wg[tid];
            const float4* xp = reinterpret_cast<const float4*>(
                x + ((size_t)b * IC_ + (i0 + ii + 1)) * ID_);
            xna = xp[0];
            xnb = xp[1];
        }

        // x row, UNNORMALIZED (normalization cancels exactly: NNMF update is
        // scale-invariant in x up to the final h normalization, and alpha's
        // per-(b,i) x-scale cancels in the alpha normalization over oc).
        float xr[ID_];
        xr[0] = xa.x; xr[1] = xa.y; xr[2] = xa.z; xr[3] = xa.w;
        xr[4] = xb.x; xr[5] = xb.y; xr[6] = xb.z; xr[7] = xb.w;

        // This warp's capsule weights as fp32x2 pairs (uniform address across
        // the warp: smem broadcast, conflict-free). Row d = 4 x 16B vectors.
        const ulonglong2* wp = reinterpret_cast<const ulonglong2*>(
            sw[pb] + c * (ID_ * OD_));

        // ---- NNMF iterations (multiplicative update, renorm deferred) ----
        //   s_d     = sum_e cur[e] * w[d,e]
        //   cur[e] *= sum_d x[d] * w[d,e] / (s_d + EPS)
        ull cur2[OD_ / 2];
        #pragma unroll
        for (int k = 0; k < OD_ / 2; k++)
            cur2[k] = 0x3D8000003D800000ULL;  // (1/16, 1/16)

        for (int it = 0; it < N_ITER_; it++) {
            ull acc2[OD_ / 2];
            #pragma unroll
            for (int k = 0; k < OD_ / 2; k++) acc2[k] = 0ULL;

            #pragma unroll
            for (int d = 0; d < ID_; d++) {
                ull wv[OD_ / 2];
                #pragma unroll
                for (int q = 0; q < 4; q++) {
                    ulonglong2 v = wp[d * 4 + q];
                    wv[2 * q + 0] = v.x;
                    wv[2 * q + 1] = v.y;
                }
                ull s2 = 0ULL;
                #pragma unroll
                for (int k = 0; k < OD_ / 2; k++) s2 = FMA2(cur2[k], wv[k], s2);
                float t = xr[d] * frcp(SUM2(s2) + EPS_);
                ull t2 = PACK2(t, t);
                #pragma unroll
                for (int k = 0; k < OD_ / 2; k++) acc2[k] = FMA2(wv[k], t2, acc2[k]);
            }
            #pragma unroll
            for (int k = 0; k < OD_ / 2; k++) cur2[k] = MUL2(cur2[k], acc2[k]);
        }

        // ---- h normalization factor (applied lazily) ----
        ull hs2 = ADD2(ADD2(ADD2(cur2[0], cur2[1]), ADD2(cur2[2], cur2[3])),
                       ADD2(ADD2(cur2[4], cur2[5]), ADD2(cur2[6], cur2[7])));
        float hr = frcp(SUM2(hs2) + EPS_);

        // ---- alpha = hr * sum_d x[d] * (cur . w[d,:]) ----
        float A = 0.0f;
        #pragma unroll
        for (int d = 0; d < ID_; d++) {
            ull s2 = 0ULL;
            #pragma unroll
            for (int q = 0; q < 4; q++) {
                ulonglong2 v = wp[d * 4 + q];
                s2 = FMA2(cur2[2 * q + 0], v.x, s2);
                s2 = FMA2(cur2[2 * q + 1], v.y, s2);
            }
            A = fmaf(xr[d], SUM2(s2), A);
        }
        float alpha = hr * A;

        salpha[c][b] = alpha;
        __syncthreads();

        float asum = 0.0f;
        #pragma unroll
        for (int cc = 0; cc < OC_; cc++) asum += salpha[cc][b];
        float an = alpha * frcp(asum + EPS_);

        // oacc += h * an = cur * (hr * an)
        float sc = hr * an;
        ull sc2 = PACK2(sc, sc);
        #pragma unroll
        for (int k = 0; k < OD_ / 2; k++) oacc2[k] = FMA2(cur2[k], sc2, oacc2[k]);

        // ---- Commit prefetched weights to the other buffer ----
        if (ii + 1 < GI_) {
            reinterpret_cast<float4*>(sw[pb ^ 1])[tid] = wnext;
            __syncthreads();  // salpha reads done + next weights visible
            xa = xna; xb = xnb;
            pb ^= 1;
        }
    }

    // ---- Accumulate this CTA's contribution into out[b,c,:] ----
    float* op = out + ((size_t)b * OC_ + c) * OD_;
    #pragma unroll
    for (int k = 0; k < OD_ / 2; k++) {
        atomicAdd(op + 2 * k + 0, LO2(oacc2[k]));
        atomicAdd(op + 2 * k + 1, HI2(oacc2[k]));
    }
}

extern "C" void kernel_launch(void* const* d_in, const int* in_sizes, int n_in,
                              void* d_out, int out_size)
{
    const float* x = (const float*)d_in[0];
    const float* w = (const float*)d_in[1];
    // Defensive: identify tensors by size (x = 294912, w = 1474560).
    if (n_in >= 2 && in_sizes[0] == IC_ * OC_ * ID_ * OD_) {
        const float* t = x; x = w; w = t;
    }
    float* out = (float*)d_out;

    caps_zero_kernel<<<(out_size + 255) / 256, 256>>>(out, out_size);
    caps_main_kernel<<<NBLK_, NTHR_>>>(x, w, out);
}